// round 4
// baseline (speedup 1.0000x reference)
#include <cuda_runtime.h>
#include <math.h>

#define BB 2
#define LL 2048
#define DD 2048
#define HH 16
#define KVH 4
#define HD 128
#define REP (HH / KVH)

// -------- scratch (device globals; no allocation allowed) --------
__device__ float g_q[BB * LL * DD];          // (B*L, H*HD) after q proj + rope
__device__ float g_k[BB * LL * KVH * HD];    // (B*L, KV*HD)
__device__ float g_v[BB * LL * KVH * HD];
__device__ float g_o[BB * LL * DD];          // attention output (B,L,D)

// ============================================================
// SGEMM NT: C[M,N] = A[M,Kd] * Bm[N,Kd]^T   (all row-major, fp32)
// BM=BN=128, BK=8, 256 threads, 8x8 per thread.
// M,N divisible by 128; Kd divisible by 8 (true for all our shapes).
// ============================================================
__global__ __launch_bounds__(256) void sgemm_nt(
    const float* __restrict__ A, const float* __restrict__ Bm,
    float* __restrict__ C, int N, int Kd)
{
    __shared__ float As[8][132];
    __shared__ float Bs[8][132];

    int tid = threadIdx.x;
    int tx = tid & 15;
    int ty = tid >> 4;

    int rA = (blockIdx.y << 7) + (tid >> 1);
    int rB = (blockIdx.x << 7) + (tid >> 1);
    int c4 = (tid & 1) * 4;
    int sr = tid >> 1;

    float acc[8][8];
#pragma unroll
    for (int i = 0; i < 8; i++)
#pragma unroll
        for (int j = 0; j < 8; j++) acc[i][j] = 0.f;

    const float* aPtr = A + (size_t)rA * Kd + c4;
    const float* bPtr = Bm + (size_t)rB * Kd + c4;

    for (int k0 = 0; k0 < Kd; k0 += 8) {
        float4 av = *(const float4*)(aPtr + k0);
        float4 bv = *(const float4*)(bPtr + k0);
        __syncthreads();
        As[c4 + 0][sr] = av.x; As[c4 + 1][sr] = av.y;
        As[c4 + 2][sr] = av.z; As[c4 + 3][sr] = av.w;
        Bs[c4 + 0][sr] = bv.x; Bs[c4 + 1][sr] = bv.y;
        Bs[c4 + 2][sr] = bv.z; Bs[c4 + 3][sr] = bv.w;
        __syncthreads();
#pragma unroll
        for (int kk = 0; kk < 8; kk++) {
            float4 a0 = *(const float4*)&As[kk][ty * 8];
            float4 a1 = *(const float4*)&As[kk][ty * 8 + 4];
            float4 b0 = *(const float4*)&Bs[kk][tx * 8];
            float4 b1 = *(const float4*)&Bs[kk][tx * 8 + 4];
            float ar[8] = {a0.x, a0.y, a0.z, a0.w, a1.x, a1.y, a1.z, a1.w};
            float br[8] = {b0.x, b0.y, b0.z, b0.w, b1.x, b1.y, b1.z, b1.w};
#pragma unroll
            for (int i = 0; i < 8; i++)
#pragma unroll
                for (int j = 0; j < 8; j++) acc[i][j] = fmaf(ar[i], br[j], acc[i][j]);
        }
    }

    float* cp = C + (size_t)((blockIdx.y << 7) + ty * 8) * N + (blockIdx.x << 7) + tx * 8;
#pragma unroll
    for (int i = 0; i < 8; i++) {
        float4 o0 = {acc[i][0], acc[i][1], acc[i][2], acc[i][3]};
        float4 o1 = {acc[i][4], acc[i][5], acc[i][6], acc[i][7]};
        *(float4*)(cp + (size_t)i * N) = o0;
        *(float4*)(cp + (size_t)i * N + 4) = o1;
    }
}

// ============================================================
// RoPE in place. buf layout (B*L, nH*HD). One thread per (bl, h, pair j).
// ============================================================
__global__ void rope_kernel(float* __restrict__ buf, int nH, int total)
{
    int idx = blockIdx.x * blockDim.x + threadIdx.x;
    if (idx >= total) return;
    int j = idx & 63;
    int h = (idx >> 6) % nH;
    int bl = idx / (64 * nH);
    int l = bl & (LL - 1);

    // inv_freq = 10000^(-j/64) ; ln(10000)/64
    float inv = __expf(-(float)j * 0.14391156531522784f);
    float ang = (float)l * inv;
    float s, c;
    sincosf(ang, &s, &c);

    float* p = buf + (size_t)bl * (nH * HD) + h * HD + 2 * j;
    float x1 = p[0], x2 = p[1];
    p[0] = x1 * c - x2 * s;
    p[1] = x1 * s + x2 * c;
}

// ============================================================
// Flash attention (causal, GQA). BM=BN=64, 256 threads (16x16).
// Thread (tx,ty): S rows ty*4+i, S cols tx+16*j ; O cols tx+16*c (c<8).
// Dynamic smem: Qs[64][132] | KV (union: Kt[128][65] / Vs[64][132]) | Ps[64][68]
// ============================================================
#define QS_STRIDE 132
#define KT_STRIDE 65
#define VS_STRIDE 132
#define PS_STRIDE 68
#define SM_QS 0
#define SM_KV 8448
#define SM_PS 16896
#define FLASH_SMEM_FLOATS (16896 + 64 * PS_STRIDE)
#define FLASH_SMEM_BYTES (FLASH_SMEM_FLOATS * 4)

__global__ __launch_bounds__(256, 2) void flash_kernel(
    const float* __restrict__ gq, const float* __restrict__ gk,
    const float* __restrict__ gv, float* __restrict__ go)
{
    extern __shared__ float sm[];
    float* Qs = sm + SM_QS;
    float* KV = sm + SM_KV;
    float* Ps = sm + SM_PS;

    const int qb = blockIdx.x << 6;
    const int h = blockIdx.y;
    const int b = blockIdx.z;
    const int kvh = h >> 2;  // REP = 4
    const int tid = threadIdx.x;
    const int tx = tid & 15;
    const int ty = tid >> 4;
    const float scale = 0.08838834764831845f;  // 1/sqrt(128)

    // ---- load Q tile (64 x 128) ----
    const float* qbase = gq + (size_t)(b * LL + qb) * DD + h * HD;
#pragma unroll
    for (int m = 0; m < 8; m++) {
        int f = tid + m * 256;           // float4 index, 2048 total
        int r = f >> 5;
        int c = (f & 31) * 4;
        float4 v = *(const float4*)(qbase + (size_t)r * DD + c);
        *(float4*)&Qs[r * QS_STRIDE + c] = v;
    }

    float acc[4][8];
    float m_i[4], l_i[4];
#pragma unroll
    for (int i = 0; i < 4; i++) {
        m_i[i] = -INFINITY;
        l_i[i] = 0.f;
#pragma unroll
        for (int c = 0; c < 8; c++) acc[i][c] = 0.f;
    }

    const int lastTile = blockIdx.x;
    for (int kt = 0; kt <= lastTile; kt++) {
        const int kb = kt << 6;
        __syncthreads();  // prior PV reads of KV done (also covers Q load on iter 0)

        // ---- load K tile transposed: Kt[d][seq] ----
        const float* kbase = gk + (size_t)(b * LL + kb) * (KVH * HD) + kvh * HD;
#pragma unroll
        for (int m = 0; m < 8; m++) {
            int f = tid + m * 256;
            int r = f >> 5;            // seq row 0..63
            int c = (f & 31) * 4;      // d
            float4 v = *(const float4*)(kbase + (size_t)r * (KVH * HD) + c);
            KV[(c + 0) * KT_STRIDE + r] = v.x;
            KV[(c + 1) * KT_STRIDE + r] = v.y;
            KV[(c + 2) * KT_STRIDE + r] = v.z;
            KV[(c + 3) * KT_STRIDE + r] = v.w;
        }
        __syncthreads();

        // ---- S = Q K^T ----
        float s[4][4];
#pragma unroll
        for (int i = 0; i < 4; i++)
#pragma unroll
            for (int j = 0; j < 4; j++) s[i][j] = 0.f;

#pragma unroll 4
        for (int d = 0; d < 128; d++) {
            float rq[4], rk[4];
#pragma unroll
            for (int i = 0; i < 4; i++) rq[i] = Qs[(ty * 4 + i) * QS_STRIDE + d];
#pragma unroll
            for (int j = 0; j < 4; j++) rk[j] = KV[d * KT_STRIDE + tx + 16 * j];
#pragma unroll
            for (int i = 0; i < 4; i++)
#pragma unroll
                for (int j = 0; j < 4; j++) s[i][j] = fmaf(rq[i], rk[j], s[i][j]);
        }

        // scale + causal mask (only diag tile can mask)
        if (kt == lastTile) {
#pragma unroll
            for (int i = 0; i < 4; i++) {
                int grow = qb + ty * 4 + i;
#pragma unroll
                for (int j = 0; j < 4; j++) {
                    int gcol = kb + tx + 16 * j;
                    s[i][j] = (gcol <= grow) ? s[i][j] * scale : -INFINITY;
                }
            }
        } else {
#pragma unroll
            for (int i = 0; i < 4; i++)
#pragma unroll
                for (int j = 0; j < 4; j++) s[i][j] *= scale;
        }

        // ---- online softmax update ----
#pragma unroll
        for (int i = 0; i < 4; i++) {
            float tm = fmaxf(fmaxf(s[i][0], s[i][1]), fmaxf(s[i][2], s[i][3]));
#pragma unroll
            for (int off = 8; off >= 1; off >>= 1)
                tm = fmaxf(tm, __shfl_xor_sync(0xffffffffu, tm, off));
            float mn = fmaxf(m_i[i], tm);
            float corr = __expf(m_i[i] - mn);
            m_i[i] = mn;
            float psum = 0.f;
#pragma unroll
            for (int j = 0; j < 4; j++) {
                float p = __expf(s[i][j] - mn);
                Ps[(ty * 4 + i) * PS_STRIDE + tx + 16 * j] = p;
                psum += p;
            }
#pragma unroll
            for (int off = 8; off >= 1; off >>= 1)
                psum += __shfl_xor_sync(0xffffffffu, psum, off);
            l_i[i] = l_i[i] * corr + psum;
#pragma unroll
            for (int c = 0; c < 8; c++) acc[i][c] *= corr;
        }
        __syncthreads();  // Ps written; all KV(K) reads done

        // ---- load V tile: Vs[seq][d] ----
        const float* vbase = gv + (size_t)(b * LL + kb) * (KVH * HD) + kvh * HD;
#pragma unroll
        for (int m = 0; m < 8; m++) {
            int f = tid + m * 256;
            int r = f >> 5;
            int c = (f & 31) * 4;
            float4 v = *(const float4*)(vbase + (size_t)r * (KVH * HD) + c);
            *(float4*)&KV[r * VS_STRIDE + c] = v;
        }
        __syncthreads();

        // ---- O += P V ----
#pragma unroll 2
        for (int jj = 0; jj < 64; jj++) {
            float pv[4];
#pragma unroll
            for (int i = 0; i < 4; i++) pv[i] = Ps[(ty * 4 + i) * PS_STRIDE + jj];
#pragma unroll
            for (int c = 0; c < 8; c++) {
                float vv = KV[jj * VS_STRIDE + tx + 16 * c];
#pragma unroll
                for (int i = 0; i < 4; i++) acc[i][c] = fmaf(pv[i], vv, acc[i][c]);
            }
        }
    }

    // ---- epilogue ----
    float* obase = go + (size_t)(b * LL + qb) * DD + h * HD;
#pragma unroll
    for (int i = 0; i < 4; i++) {
        float inv = 1.f / l_i[i];
#pragma unroll
        for (int c = 0; c < 8; c++)
            obase[(size_t)(ty * 4 + i) * DD + tx + 16 * c] = acc[i][c] * inv;
    }
}

// ============================================================
extern "C" void kernel_launch(void* const* d_in, const int* in_sizes, int n_in,
                              void* d_out, int out_size)
{
    const float* x  = (const float*)d_in[0];
    const float* wq = (const float*)d_in[1];
    const float* wk = (const float*)d_in[2];
    const float* wv = (const float*)d_in[3];
    const float* wo = (const float*)d_in[4];
    float* out = (float*)d_out;

    float *qp, *kp, *vp, *op;
    cudaGetSymbolAddress((void**)&qp, g_q);
    cudaGetSymbolAddress((void**)&kp, g_k);
    cudaGetSymbolAddress((void**)&vp, g_v);
    cudaGetSymbolAddress((void**)&op, g_o);

    cudaFuncSetAttribute(flash_kernel, cudaFuncAttributeMaxDynamicSharedMemorySize,
                         FLASH_SMEM_BYTES);

    const int M = BB * LL;  // 4096

    dim3 gQ(DD / 128, M / 128);            // 16 x 32
    dim3 gKV((KVH * HD) / 128, M / 128);   // 4 x 32

    sgemm_nt<<<gQ, 256>>>(x, wq, qp, DD, DD);
    sgemm_nt<<<gKV, 256>>>(x, wk, kp, KVH * HD, DD);
    sgemm_nt<<<gKV, 256>>>(x, wv, vp, KVH * HD, DD);

    int totQ = M * HH * 64;
    int totK = M * KVH * 64;
    rope_kernel<<<(totQ + 255) / 256, 256>>>(qp, HH, totQ);
    rope_kernel<<<(totK + 255) / 256, 256>>>(kp, KVH, totK);

    flash_kernel<<<dim3(LL / 64, HH, BB), 256, FLASH_SMEM_BYTES>>>(qp, kp, vp, op);

    sgemm_nt<<<gQ, 256>>>(op, wo, out, DD, DD);
}

// round 10
// speedup vs baseline: 1.6988x; 1.6988x over previous
#include <cuda_runtime.h>
#include <math.h>
#include <stdint.h>

#define BB 2
#define LL 2048
#define DD 2048
#define HH 16
#define KVH 4
#define HD 128

// -------- scratch (device globals; no allocation allowed) --------
__device__ __align__(256) float g_q[BB * LL * DD];
__device__ __align__(256) float g_k[BB * LL * KVH * HD];
__device__ __align__(256) float g_v[BB * LL * KVH * HD];
__device__ __align__(256) float g_o[BB * LL * DD];

// ============================================================
// mma.sync tf32 helpers (base-arch PTX; compiles for sm_103)
// ============================================================
__device__ __forceinline__ uint32_t f2tf32(float f) {
    uint32_t u;
    asm("cvt.rna.tf32.f32 %0, %1;" : "=r"(u) : "f"(f));
    return u;
}
__device__ __forceinline__ void mma_tf32(float c[4], const uint32_t a[4],
                                         const uint32_t b[2]) {
    asm volatile(
        "mma.sync.aligned.m16n8k8.row.col.f32.tf32.tf32.f32 "
        "{%0,%1,%2,%3}, {%4,%5,%6,%7}, {%8,%9}, {%0,%1,%2,%3};"
        : "+f"(c[0]), "+f"(c[1]), "+f"(c[2]), "+f"(c[3])
        : "r"(a[0]), "r"(a[1]), "r"(a[2]), "r"(a[3]), "r"(b[0]), "r"(b[1]));
}

// ============================================================
// TF32 mma.sync GEMM NT: C[M,N] = A[M,2048] * Bm[N,2048]^T (fp32 in/out)
// BM=BN=128, BK=32. 256 thr, 8 warps (2 row x 4 col), warp tile 64x32.
// smem: double-buffered k-major tiles s[k][row], stride 132, tf32 bits.
// ============================================================
#define KSTRIDE 132
#define STG_U32 (32 * KSTRIDE)            // one matrix tile: 4224 u32
#define STAGE_U32 (2 * STG_U32)           // A + B per stage
#define MMA_GEMM_SMEM (2 * STAGE_U32 * 4) // bytes = 67584

__global__ __launch_bounds__(256) void mma_gemm_nt(
    const float* __restrict__ A, const float* __restrict__ Bm,
    float* __restrict__ C, int N)
{
    extern __shared__ uint32_t smu[];

    const int tid = threadIdx.x;
    const int wid = tid >> 5;
    const int lane = tid & 31;
    const int g = lane >> 2;    // groupID (row within 8)
    const int tig = lane & 3;   // thread-in-group
    const int wm = wid & 1;     // warp row (0..1) -> 64 rows
    const int wn = wid >> 1;    // warp col (0..3) -> 32 cols
    const int bm = blockIdx.y, bn = blockIdx.x;

    // per-thread gmem slots: 4 float4 of A, 4 of B per 32-k chunk
    const float* ga[4];
    const float* gb[4];
    int srow[4], scol[4];
#pragma unroll
    for (int j = 0; j < 4; j++) {
        int f = tid + j * 256;   // 0..1023
        int r = f >> 3;          // tile row 0..127
        int cq = f & 7;          // float4 within 32-wide k-chunk
        ga[j] = A + (size_t)(bm * 128 + r) * 2048 + cq * 4;
        gb[j] = Bm + (size_t)(bn * 128 + r) * 2048 + cq * 4;
        srow[j] = r;
        scol[j] = cq * 4;
    }

    float acc[4][4][4];
#pragma unroll
    for (int i = 0; i < 4; i++)
#pragma unroll
        for (int j = 0; j < 4; j++)
#pragma unroll
            for (int t = 0; t < 4; t++) acc[i][j][t] = 0.f;

    float4 pa[4], pb[4];
#pragma unroll
    for (int j = 0; j < 4; j++) { pa[j] = *(const float4*)ga[j]; pb[j] = *(const float4*)gb[j]; }

    for (int ch = 0; ch < 64; ch++) {
        const int b = ch & 1;
        uint32_t* sA = smu + b * STAGE_U32;
        uint32_t* sB = sA + STG_U32;

        // stage (transpose to k-major, convert to tf32)
#pragma unroll
        for (int j = 0; j < 4; j++) {
            sA[(scol[j] + 0) * KSTRIDE + srow[j]] = f2tf32(pa[j].x);
            sA[(scol[j] + 1) * KSTRIDE + srow[j]] = f2tf32(pa[j].y);
            sA[(scol[j] + 2) * KSTRIDE + srow[j]] = f2tf32(pa[j].z);
            sA[(scol[j] + 3) * KSTRIDE + srow[j]] = f2tf32(pa[j].w);
            sB[(scol[j] + 0) * KSTRIDE + srow[j]] = f2tf32(pb[j].x);
            sB[(scol[j] + 1) * KSTRIDE + srow[j]] = f2tf32(pb[j].y);
            sB[(scol[j] + 2) * KSTRIDE + srow[j]] = f2tf32(pb[j].z);
            sB[(scol[j] + 3) * KSTRIDE + srow[j]] = f2tf32(pb[j].w);
        }
        __syncthreads();

        // prefetch next chunk
        if (ch + 1 < 64) {
#pragma unroll
            for (int j = 0; j < 4; j++) {
                pa[j] = *(const float4*)(ga[j] + (ch + 1) * 32);
                pb[j] = *(const float4*)(gb[j] + (ch + 1) * 32);
            }
        }

        // compute: 4 k-steps of 8
#pragma unroll
        for (int ks = 0; ks < 4; ks++) {
            uint32_t afr[4][4], bfr[4][2];
            const int k0 = ks * 8 + tig;
#pragma unroll
            for (int mb = 0; mb < 4; mb++) {
                int rb = wm * 64 + mb * 16 + g;
                afr[mb][0] = sA[k0 * KSTRIDE + rb];
                afr[mb][1] = sA[k0 * KSTRIDE + rb + 8];
                afr[mb][2] = sA[(k0 + 4) * KSTRIDE + rb];
                afr[mb][3] = sA[(k0 + 4) * KSTRIDE + rb + 8];
            }
#pragma unroll
            for (int nb = 0; nb < 4; nb++) {
                int nbse = wn * 32 + nb * 8 + g;
                bfr[nb][0] = sB[k0 * KSTRIDE + nbse];
                bfr[nb][1] = sB[(k0 + 4) * KSTRIDE + nbse];
            }
#pragma unroll
            for (int mb = 0; mb < 4; mb++)
#pragma unroll
                for (int nb = 0; nb < 4; nb++)
                    mma_tf32(acc[mb][nb], afr[mb], bfr[nb]);
        }
        __syncthreads();
    }

    // epilogue
#pragma unroll
    for (int mb = 0; mb < 4; mb++) {
        int row = bm * 128 + wm * 64 + mb * 16 + g;
#pragma unroll
        for (int nb = 0; nb < 4; nb++) {
            int col = bn * 128 + wn * 32 + nb * 8 + tig * 2;
            float2 v0 = {acc[mb][nb][0], acc[mb][nb][1]};
            float2 v1 = {acc[mb][nb][2], acc[mb][nb][3]};
            *(float2*)(C + (size_t)row * N + col) = v0;
            *(float2*)(C + (size_t)(row + 8) * N + col) = v1;
        }
    }
}

// ============================================================
// RoPE in place. buf layout (B*L, nH*HD). One thread per (bl, h, pair j).
// ============================================================
__global__ void rope_kernel(float* __restrict__ buf, int nH, int total)
{
    int idx = blockIdx.x * blockDim.x + threadIdx.x;
    if (idx >= total) return;
    int j = idx & 63;
    int h = (idx >> 6) % nH;
    int bl = idx / (64 * nH);
    int l = bl & (LL - 1);

    float inv = __expf(-(float)j * 0.14391156531522784f);  // 10000^(-j/64)
    float ang = (float)l * inv;
    float s, c;
    sincosf(ang, &s, &c);

    float* p = buf + (size_t)bl * (nH * HD) + h * HD + 2 * j;
    float x1 = p[0], x2 = p[1];
    p[0] = x1 * c - x2 * s;
    p[1] = x1 * s + x2 * c;
}

// ============================================================
// Flash attention (causal, GQA). BM=BN=64, 256 threads (16x16). fp32.
// ============================================================
#define QS_STRIDE 132
#define KT_STRIDE 65
#define VS_STRIDE 132
#define PS_STRIDE 68
#define SM_QS 0
#define SM_KV 8448
#define SM_PS 16896
#define FLASH_SMEM_FLOATS (16896 + 64 * PS_STRIDE)
#define FLASH_SMEM_BYTES (FLASH_SMEM_FLOATS * 4)

__global__ __launch_bounds__(256, 2) void flash_kernel(
    const float* __restrict__ gq, const float* __restrict__ gk,
    const float* __restrict__ gv, float* __restrict__ go)
{
    extern __shared__ float sm[];
    float* Qs = sm + SM_QS;
    float* KV = sm + SM_KV;
    float* Ps = sm + SM_PS;

    const int qb = blockIdx.x << 6;
    const int h = blockIdx.y;
    const int b = blockIdx.z;
    const int kvh = h >> 2;
    const int tid = threadIdx.x;
    const int tx = tid & 15;
    const int ty = tid >> 4;
    const float scale = 0.08838834764831845f;  // 1/sqrt(128)

    const float* qbase = gq + (size_t)(b * LL + qb) * DD + h * HD;
#pragma unroll
    for (int m = 0; m < 8; m++) {
        int f = tid + m * 256;
        int r = f >> 5;
        int c = (f & 31) * 4;
        float4 v = *(const float4*)(qbase + (size_t)r * DD + c);
        *(float4*)&Qs[r * QS_STRIDE + c] = v;
    }

    float acc[4][8];
    float m_i[4], l_i[4];
#pragma unroll
    for (int i = 0; i < 4; i++) {
        m_i[i] = -INFINITY;
        l_i[i] = 0.f;
#pragma unroll
        for (int c = 0; c < 8; c++) acc[i][c] = 0.f;
    }

    const int lastTile = blockIdx.x;
    for (int kt = 0; kt <= lastTile; kt++) {
        const int kb = kt << 6;
        __syncthreads();

        const float* kbase = gk + (size_t)(b * LL + kb) * (KVH * HD) + kvh * HD;
#pragma unroll
        for (int m = 0; m < 8; m++) {
            int f = tid + m * 256;
            int r = f >> 5;
            int c = (f & 31) * 4;
            float4 v = *(const float4*)(kbase + (size_t)r * (KVH * HD) + c);
            KV[(c + 0) * KT_STRIDE + r] = v.x;
            KV[(c + 1) * KT_STRIDE + r] = v.y;
            KV[(c + 2) * KT_STRIDE + r] = v.z;
            KV[(c + 3) * KT_STRIDE + r] = v.w;
        }
        __syncthreads();

        float s[4][4];
#pragma unroll
        for (int i = 0; i < 4; i++)
#pragma unroll
            for (int j = 0; j < 4; j++) s[i][j] = 0.f;

#pragma unroll 4
        for (int d = 0; d < 128; d++) {
            float rq[4], rk[4];
#pragma unroll
            for (int i = 0; i < 4; i++) rq[i] = Qs[(ty * 4 + i) * QS_STRIDE + d];
#pragma unroll
            for (int j = 0; j < 4; j++) rk[j] = KV[d * KT_STRIDE + tx + 16 * j];
#pragma unroll
            for (int i = 0; i < 4; i++)
#pragma unroll
                for (int j = 0; j < 4; j++) s[i][j] = fmaf(rq[i], rk[j], s[i][j]);
        }

        if (kt == lastTile) {
#pragma unroll
            for (int i = 0; i < 4; i++) {
                int grow = qb + ty * 4 + i;
#pragma unroll
                for (int j = 0; j < 4; j++) {
                    int gcol = kb + tx + 16 * j;
                    s[i][j] = (gcol <= grow) ? s[i][j] * scale : -INFINITY;
                }
            }
        } else {
#pragma unroll
            for (int i = 0; i < 4; i++)
#pragma unroll
                for (int j = 0; j < 4; j++) s[i][j] *= scale;
        }

#pragma unroll
        for (int i = 0; i < 4; i++) {
            float tm = fmaxf(fmaxf(s[i][0], s[i][1]), fmaxf(s[i][2], s[i][3]));
#pragma unroll
            for (int off = 8; off >= 1; off >>= 1)
                tm = fmaxf(tm, __shfl_xor_sync(0xffffffffu, tm, off));
            float mn = fmaxf(m_i[i], tm);
            float corr = __expf(m_i[i] - mn);
            m_i[i] = mn;
            float psum = 0.f;
#pragma unroll
            for (int j = 0; j < 4; j++) {
                float p = __expf(s[i][j] - mn);
                Ps[(ty * 4 + i) * PS_STRIDE + tx + 16 * j] = p;
                psum += p;
            }
#pragma unroll
            for (int off = 8; off >= 1; off >>= 1)
                psum += __shfl_xor_sync(0xffffffffu, psum, off);
            l_i[i] = l_i[i] * corr + psum;
#pragma unroll
            for (int c = 0; c < 8; c++) acc[i][c] *= corr;
        }
        __syncthreads();

        const float* vbase = gv + (size_t)(b * LL + kb) * (KVH * HD) + kvh * HD;
#pragma unroll
        for (int m = 0; m < 8; m++) {
            int f = tid + m * 256;
            int r = f >> 5;
            int c = (f & 31) * 4;
            float4 v = *(const float4*)(vbase + (size_t)r * (KVH * HD) + c);
            *(float4*)&KV[r * VS_STRIDE + c] = v;
        }
        __syncthreads();

#pragma unroll 2
        for (int jj = 0; jj < 64; jj++) {
            float pv[4];
#pragma unroll
            for (int i = 0; i < 4; i++) pv[i] = Ps[(ty * 4 + i) * PS_STRIDE + jj];
#pragma unroll
            for (int c = 0; c < 8; c++) {
                float vv = KV[jj * VS_STRIDE + tx + 16 * c];
#pragma unroll
                for (int i = 0; i < 4; i++) acc[i][c] = fmaf(pv[i], vv, acc[i][c]);
            }
        }
    }

    float* obase = go + (size_t)(b * LL + qb) * DD + h * HD;
#pragma unroll
    for (int i = 0; i < 4; i++) {
        float inv = 1.f / l_i[i];
#pragma unroll
        for (int c = 0; c < 8; c++)
            obase[(size_t)(ty * 4 + i) * DD + tx + 16 * c] = acc[i][c] * inv;
    }
}

// ============================================================
extern "C" void kernel_launch(void* const* d_in, const int* in_sizes, int n_in,
                              void* d_out, int out_size)
{
    const float* x  = (const float*)d_in[0];
    const float* wq = (const float*)d_in[1];
    const float* wk = (const float*)d_in[2];
    const float* wv = (const float*)d_in[3];
    const float* wo = (const float*)d_in[4];
    float* out = (float*)d_out;

    float *qp, *kp, *vp, *op;
    cudaGetSymbolAddress((void**)&qp, g_q);
    cudaGetSymbolAddress((void**)&kp, g_k);
    cudaGetSymbolAddress((void**)&vp, g_v);
    cudaGetSymbolAddress((void**)&op, g_o);

    cudaFuncSetAttribute(mma_gemm_nt, cudaFuncAttributeMaxDynamicSharedMemorySize,
                         MMA_GEMM_SMEM);
    cudaFuncSetAttribute(flash_kernel, cudaFuncAttributeMaxDynamicSharedMemorySize,
                         FLASH_SMEM_BYTES);

    const int M = BB * LL;  // 4096

    mma_gemm_nt<<<dim3(DD / 128, M / 128), 256, MMA_GEMM_SMEM>>>(x, wq, qp, DD);
    mma_gemm_nt<<<dim3((KVH * HD) / 128, M / 128), 256, MMA_GEMM_SMEM>>>(x, wk, kp, KVH * HD);
    mma_gemm_nt<<<dim3((KVH * HD) / 128, M / 128), 256, MMA_GEMM_SMEM>>>(x, wv, vp, KVH * HD);

    int totQ = M * HH * 64;
    int totK = M * KVH * 64;
    rope_kernel<<<(totQ + 255) / 256, 256>>>(qp, HH, totQ);
    rope_kernel<<<(totK + 255) / 256, 256>>>(kp, KVH, totK);

    flash_kernel<<<dim3(LL / 64, HH, BB), 256, FLASH_SMEM_BYTES>>>(qp, kp, vp, op);

    mma_gemm_nt<<<dim3(DD / 128, M / 128), 256, MMA_GEMM_SMEM>>>(op, wo, out, DD);
}

// round 16
// speedup vs baseline: 2.8049x; 1.6511x over previous
#include <cuda_runtime.h>
#include <math.h>
#include <stdint.h>

#define BB 2
#define LL 2048
#define DD 2048
#define HH 16
#define KVH 4
#define HD 128

// -------- scratch (device globals; no allocation allowed) --------
__device__ __align__(256) float g_q[BB * LL * DD];
__device__ __align__(256) float g_k[BB * LL * KVH * HD];
__device__ __align__(256) float g_v[BB * LL * KVH * HD];
__device__ __align__(256) float g_o[BB * LL * DD];

// ============================================================
// mma.sync tf32 helpers (base-arch PTX; compiles for sm_103)
// ============================================================
__device__ __forceinline__ uint32_t f2tf32(float f) {
    uint32_t u;
    asm("cvt.rna.tf32.f32 %0, %1;" : "=r"(u) : "f"(f));
    return u;
}
__device__ __forceinline__ void mma_tf32(float c[4], const uint32_t a[4],
                                         const uint32_t b[2]) {
    asm volatile(
        "mma.sync.aligned.m16n8k8.row.col.f32.tf32.tf32.f32 "
        "{%0,%1,%2,%3}, {%4,%5,%6,%7}, {%8,%9}, {%0,%1,%2,%3};"
        : "+f"(c[0]), "+f"(c[1]), "+f"(c[2]), "+f"(c[3])
        : "r"(a[0]), "r"(a[1]), "r"(a[2]), "r"(a[3]), "r"(b[0]), "r"(b[1]));
}

// ============================================================
// TF32 mma.sync GEMM NT: C[M,N] = A[M,2048] * Bm[N,2048]^T (fp32 in/out)
// (validated round 10 — unchanged)
// ============================================================
#define KSTRIDE 132
#define STG_U32 (32 * KSTRIDE)
#define STAGE_U32 (2 * STG_U32)
#define MMA_GEMM_SMEM (2 * STAGE_U32 * 4)

__global__ __launch_bounds__(256) void mma_gemm_nt(
    const float* __restrict__ A, const float* __restrict__ Bm,
    float* __restrict__ C, int N)
{
    extern __shared__ uint32_t smu[];

    const int tid = threadIdx.x;
    const int wid = tid >> 5;
    const int lane = tid & 31;
    const int g = lane >> 2;
    const int tig = lane & 3;
    const int wm = wid & 1;
    const int wn = wid >> 1;
    const int bm = blockIdx.y, bn = blockIdx.x;

    const float* ga[4];
    const float* gb[4];
    int srow[4], scol[4];
#pragma unroll
    for (int j = 0; j < 4; j++) {
        int f = tid + j * 256;
        int r = f >> 3;
        int cq = f & 7;
        ga[j] = A + (size_t)(bm * 128 + r) * 2048 + cq * 4;
        gb[j] = Bm + (size_t)(bn * 128 + r) * 2048 + cq * 4;
        srow[j] = r;
        scol[j] = cq * 4;
    }

    float acc[4][4][4];
#pragma unroll
    for (int i = 0; i < 4; i++)
#pragma unroll
        for (int j = 0; j < 4; j++)
#pragma unroll
            for (int t = 0; t < 4; t++) acc[i][j][t] = 0.f;

    float4 pa[4], pb[4];
#pragma unroll
    for (int j = 0; j < 4; j++) { pa[j] = *(const float4*)ga[j]; pb[j] = *(const float4*)gb[j]; }

    for (int ch = 0; ch < 64; ch++) {
        const int b = ch & 1;
        uint32_t* sA = smu + b * STAGE_U32;
        uint32_t* sB = sA + STG_U32;

#pragma unroll
        for (int j = 0; j < 4; j++) {
            sA[(scol[j] + 0) * KSTRIDE + srow[j]] = f2tf32(pa[j].x);
            sA[(scol[j] + 1) * KSTRIDE + srow[j]] = f2tf32(pa[j].y);
            sA[(scol[j] + 2) * KSTRIDE + srow[j]] = f2tf32(pa[j].z);
            sA[(scol[j] + 3) * KSTRIDE + srow[j]] = f2tf32(pa[j].w);
            sB[(scol[j] + 0) * KSTRIDE + srow[j]] = f2tf32(pb[j].x);
            sB[(scol[j] + 1) * KSTRIDE + srow[j]] = f2tf32(pb[j].y);
            sB[(scol[j] + 2) * KSTRIDE + srow[j]] = f2tf32(pb[j].z);
            sB[(scol[j] + 3) * KSTRIDE + srow[j]] = f2tf32(pb[j].w);
        }
        __syncthreads();

        if (ch + 1 < 64) {
#pragma unroll
            for (int j = 0; j < 4; j++) {
                pa[j] = *(const float4*)(ga[j] + (ch + 1) * 32);
                pb[j] = *(const float4*)(gb[j] + (ch + 1) * 32);
            }
        }

#pragma unroll
        for (int ks = 0; ks < 4; ks++) {
            uint32_t afr[4][4], bfr[4][2];
            const int k0 = ks * 8 + tig;
#pragma unroll
            for (int mb = 0; mb < 4; mb++) {
                int rb = wm * 64 + mb * 16 + g;
                afr[mb][0] = sA[k0 * KSTRIDE + rb];
                afr[mb][1] = sA[k0 * KSTRIDE + rb + 8];
                afr[mb][2] = sA[(k0 + 4) * KSTRIDE + rb];
                afr[mb][3] = sA[(k0 + 4) * KSTRIDE + rb + 8];
            }
#pragma unroll
            for (int nb = 0; nb < 4; nb++) {
                int nbse = wn * 32 + nb * 8 + g;
                bfr[nb][0] = sB[k0 * KSTRIDE + nbse];
                bfr[nb][1] = sB[(k0 + 4) * KSTRIDE + nbse];
            }
#pragma unroll
            for (int mb = 0; mb < 4; mb++)
#pragma unroll
                for (int nb = 0; nb < 4; nb++)
                    mma_tf32(acc[mb][nb], afr[mb], bfr[nb]);
        }
        __syncthreads();
    }

#pragma unroll
    for (int mb = 0; mb < 4; mb++) {
        int row = bm * 128 + wm * 64 + mb * 16 + g;
#pragma unroll
        for (int nb = 0; nb < 4; nb++) {
            int col = bn * 128 + wn * 32 + nb * 8 + tig * 2;
            float2 v0 = {acc[mb][nb][0], acc[mb][nb][1]};
            float2 v1 = {acc[mb][nb][2], acc[mb][nb][3]};
            *(float2*)(C + (size_t)row * N + col) = v0;
            *(float2*)(C + (size_t)(row + 8) * N + col) = v1;
        }
    }
}

// ============================================================
// RoPE in place (unchanged)
// ============================================================
__global__ void rope_kernel(float* __restrict__ buf, int nH, int total)
{
    int idx = blockIdx.x * blockDim.x + threadIdx.x;
    if (idx >= total) return;
    int j = idx & 63;
    int h = (idx >> 6) % nH;
    int bl = idx / (64 * nH);
    int l = bl & (LL - 1);

    float inv = __expf(-(float)j * 0.14391156531522784f);
    float ang = (float)l * inv;
    float s, c;
    sincosf(ang, &s, &c);

    float* p = buf + (size_t)bl * (nH * HD) + h * HD + 2 * j;
    float x1 = p[0], x2 = p[1];
    p[0] = x1 * c - x2 * s;
    p[1] = x1 * s + x2 * c;
}

// ============================================================
// Flash attention, TF32 mma.sync. BM=BN=64, 128 threads (4 warps).
// Warp w owns rows w*16 .. w*16+15 (thread rows g, g+8).
// smem (u32): sK[64][132] (seq-major, = gmem layout), sV[64][136],
//             sP[4 warps][16][68] (warp-private).
// ============================================================
#define FK_STRIDE 132
#define FV_STRIDE 136
#define FP_STRIDE 68
#define SMK 0
#define SMV (64 * FK_STRIDE)                  // 8448
#define SMP (SMV + 64 * FV_STRIDE)            // 17152
#define FLASH_SMEM_U32 (SMP + 4 * 16 * FP_STRIDE)  // 21504
#define FLASH_SMEM_BYTES (FLASH_SMEM_U32 * 4)      // 86016

__global__ __launch_bounds__(128) void flash_mma(
    const float* __restrict__ gq, const float* __restrict__ gk,
    const float* __restrict__ gv, float* __restrict__ go)
{
    extern __shared__ uint32_t smu[];

    const int tid = threadIdx.x;
    const int wid = tid >> 5;
    const int lane = tid & 31;
    const int g = lane >> 2;
    const int tig = lane & 3;
    const int qb = blockIdx.x << 6;
    const int h = blockIdx.y;
    const int b = blockIdx.z;
    const int kvh = h >> 2;
    const float scale = 0.08838834764831845f;  // 1/sqrt(128)

    // ---- preload Q fragments (rows qb + wid*16 + {g, g+8}) ----
    uint32_t qreg[16][4];
    {
        const float* qbase = gq + (size_t)(b * LL + qb + wid * 16) * DD + h * HD;
#pragma unroll
        for (int ks = 0; ks < 16; ks++) {
            qreg[ks][0] = f2tf32(qbase[(size_t)g * DD + ks * 8 + tig]);
            qreg[ks][1] = f2tf32(qbase[(size_t)(g + 8) * DD + ks * 8 + tig]);
            qreg[ks][2] = f2tf32(qbase[(size_t)g * DD + ks * 8 + tig + 4]);
            qreg[ks][3] = f2tf32(qbase[(size_t)(g + 8) * DD + ks * 8 + tig + 4]);
        }
    }

    float oacc[16][4];
#pragma unroll
    for (int i = 0; i < 16; i++)
#pragma unroll
        for (int t = 0; t < 4; t++) oacc[i][t] = 0.f;
    float m0 = -INFINITY, m1 = -INFINITY, l0 = 0.f, l1 = 0.f;

    uint32_t* sP = smu + SMP + wid * (16 * FP_STRIDE);
    const int grow0 = qb + wid * 16 + g;
    const int grow1 = grow0 + 8;

    const int lastTile = blockIdx.x;
    for (int kt = 0; kt <= lastTile; kt++) {
        const int kb = kt << 6;
        __syncthreads();  // guard prior sK/sV reads

        // ---- stage K and V tiles (direct copy, tf32 convert) ----
        {
            const float* kbase = gk + (size_t)(b * LL + kb) * (KVH * HD) + kvh * HD;
            const float* vbase = gv + (size_t)(b * LL + kb) * (KVH * HD) + kvh * HD;
#pragma unroll
            for (int m = 0; m < 16; m++) {
                int f = tid + m * 128;     // 0..2047 float4 slots
                int r = f >> 5;            // seq row 0..63
                int cq = (f & 31) * 4;     // element col
                float4 kv4 = *(const float4*)(kbase + (size_t)r * (KVH * HD) + cq);
                uint32_t* d = smu + SMK + r * FK_STRIDE + cq;
                d[0] = f2tf32(kv4.x); d[1] = f2tf32(kv4.y);
                d[2] = f2tf32(kv4.z); d[3] = f2tf32(kv4.w);
                float4 vv4 = *(const float4*)(vbase + (size_t)r * (KVH * HD) + cq);
                uint32_t* dv = smu + SMV + r * FV_STRIDE + cq;
                dv[0] = f2tf32(vv4.x); dv[1] = f2tf32(vv4.y);
                dv[2] = f2tf32(vv4.z); dv[3] = f2tf32(vv4.w);
            }
        }
        __syncthreads();

        // ---- S = Q K^T (warp rows x 64 cols) ----
        float s[8][4];
#pragma unroll
        for (int nb = 0; nb < 8; nb++)
#pragma unroll
            for (int t = 0; t < 4; t++) s[nb][t] = 0.f;

#pragma unroll
        for (int ks = 0; ks < 16; ks++) {
            const int k0 = ks * 8 + tig;
#pragma unroll
            for (int nb = 0; nb < 8; nb++) {
                uint32_t bfr[2];
                bfr[0] = smu[SMK + (nb * 8 + g) * FK_STRIDE + k0];
                bfr[1] = smu[SMK + (nb * 8 + g) * FK_STRIDE + k0 + 4];
                mma_tf32(s[nb], qreg[ks], bfr);
            }
        }

        // ---- scale + causal mask ----
        if (kt == lastTile) {
#pragma unroll
            for (int nb = 0; nb < 8; nb++) {
                int c0 = kb + nb * 8 + 2 * tig;
                s[nb][0] = (c0 <= grow0)     ? s[nb][0] * scale : -INFINITY;
                s[nb][1] = (c0 + 1 <= grow0) ? s[nb][1] * scale : -INFINITY;
                s[nb][2] = (c0 <= grow1)     ? s[nb][2] * scale : -INFINITY;
                s[nb][3] = (c0 + 1 <= grow1) ? s[nb][3] * scale : -INFINITY;
            }
        } else {
#pragma unroll
            for (int nb = 0; nb < 8; nb++)
#pragma unroll
                for (int t = 0; t < 4; t++) s[nb][t] *= scale;
        }

        // ---- online softmax (rows g and g+8; 4 lanes share a row) ----
        float tm0 = -INFINITY, tm1 = -INFINITY;
#pragma unroll
        for (int nb = 0; nb < 8; nb++) {
            tm0 = fmaxf(tm0, fmaxf(s[nb][0], s[nb][1]));
            tm1 = fmaxf(tm1, fmaxf(s[nb][2], s[nb][3]));
        }
        tm0 = fmaxf(tm0, __shfl_xor_sync(0xffffffffu, tm0, 1));
        tm0 = fmaxf(tm0, __shfl_xor_sync(0xffffffffu, tm0, 2));
        tm1 = fmaxf(tm1, __shfl_xor_sync(0xffffffffu, tm1, 1));
        tm1 = fmaxf(tm1, __shfl_xor_sync(0xffffffffu, tm1, 2));

        float mn0 = fmaxf(m0, tm0);
        float mn1 = fmaxf(m1, tm1);
        float corr0 = __expf(m0 - mn0);
        float corr1 = __expf(m1 - mn1);
        m0 = mn0; m1 = mn1;

        float ps0 = 0.f, ps1 = 0.f;
#pragma unroll
        for (int nb = 0; nb < 8; nb++) {
            float p0 = __expf(s[nb][0] - mn0);
            float p1 = __expf(s[nb][1] - mn0);
            float p2 = __expf(s[nb][2] - mn1);
            float p3 = __expf(s[nb][3] - mn1);
            ps0 += p0 + p1;
            ps1 += p2 + p3;
            int c = nb * 8 + 2 * tig;
            sP[g * FP_STRIDE + c] = f2tf32(p0);
            sP[g * FP_STRIDE + c + 1] = f2tf32(p1);
            sP[(g + 8) * FP_STRIDE + c] = f2tf32(p2);
            sP[(g + 8) * FP_STRIDE + c + 1] = f2tf32(p3);
        }
        ps0 += __shfl_xor_sync(0xffffffffu, ps0, 1);
        ps0 += __shfl_xor_sync(0xffffffffu, ps0, 2);
        ps1 += __shfl_xor_sync(0xffffffffu, ps1, 1);
        ps1 += __shfl_xor_sync(0xffffffffu, ps1, 2);
        l0 = l0 * corr0 + ps0;
        l1 = l1 * corr1 + ps1;

#pragma unroll
        for (int nb2 = 0; nb2 < 16; nb2++) {
            oacc[nb2][0] *= corr0; oacc[nb2][1] *= corr0;
            oacc[nb2][2] *= corr1; oacc[nb2][3] *= corr1;
        }
        __syncwarp();  // sP is warp-private

        // ---- O += P V ----
#pragma unroll
        for (int ks2 = 0; ks2 < 8; ks2++) {
            uint32_t afr[4];
            const int k0 = ks2 * 8 + tig;
            afr[0] = sP[g * FP_STRIDE + k0];
            afr[1] = sP[(g + 8) * FP_STRIDE + k0];
            afr[2] = sP[g * FP_STRIDE + k0 + 4];
            afr[3] = sP[(g + 8) * FP_STRIDE + k0 + 4];
#pragma unroll
            for (int nb2 = 0; nb2 < 16; nb2++) {
                uint32_t bfr[2];
                bfr[0] = smu[SMV + k0 * FV_STRIDE + nb2 * 8 + g];
                bfr[1] = smu[SMV + (k0 + 4) * FV_STRIDE + nb2 * 8 + g];
                mma_tf32(oacc[nb2], afr, bfr);
            }
        }
        __syncwarp();  // sP reads done before next tile's writes
    }

    // ---- epilogue ----
    float inv0 = 1.f / l0;
    float inv1 = 1.f / l1;
    float* ob0 = go + (size_t)(b * LL + grow0) * DD + h * HD;
    float* ob1 = go + (size_t)(b * LL + grow1) * DD + h * HD;
#pragma unroll
    for (int nb2 = 0; nb2 < 16; nb2++) {
        int c = nb2 * 8 + 2 * tig;
        float2 v0 = {oacc[nb2][0] * inv0, oacc[nb2][1] * inv0};
        float2 v1 = {oacc[nb2][2] * inv1, oacc[nb2][3] * inv1};
        *(float2*)(ob0 + c) = v0;
        *(float2*)(ob1 + c) = v1;
    }
}

// ============================================================
extern "C" void kernel_launch(void* const* d_in, const int* in_sizes, int n_in,
                              void* d_out, int out_size)
{
    const float* x  = (const float*)d_in[0];
    const float* wq = (const float*)d_in[1];
    const float* wk = (const float*)d_in[2];
    const float* wv = (const float*)d_in[3];
    const float* wo = (const float*)d_in[4];
    float* out = (float*)d_out;

    float *qp, *kp, *vp, *op;
    cudaGetSymbolAddress((void**)&qp, g_q);
    cudaGetSymbolAddress((void**)&kp, g_k);
    cudaGetSymbolAddress((void**)&vp, g_v);
    cudaGetSymbolAddress((void**)&op, g_o);

    cudaFuncSetAttribute(mma_gemm_nt, cudaFuncAttributeMaxDynamicSharedMemorySize,
                         MMA_GEMM_SMEM);
    cudaFuncSetAttribute(flash_mma, cudaFuncAttributeMaxDynamicSharedMemorySize,
                         FLASH_SMEM_BYTES);

    const int M = BB * LL;  // 4096

    mma_gemm_nt<<<dim3(DD / 128, M / 128), 256, MMA_GEMM_SMEM>>>(x, wq, qp, DD);
    mma_gemm_nt<<<dim3((KVH * HD) / 128, M / 128), 256, MMA_GEMM_SMEM>>>(x, wk, kp, KVH * HD);
    mma_gemm_nt<<<dim3((KVH * HD) / 128, M / 128), 256, MMA_GEMM_SMEM>>>(x, wv, vp, KVH * HD);

    int totQ = M * HH * 64;
    int totK = M * KVH * 64;
    rope_kernel<<<(totQ + 255) / 256, 256>>>(qp, HH, totQ);
    rope_kernel<<<(totK + 255) / 256, 256>>>(kp, KVH, totK);

    flash_mma<<<dim3(LL / 64, HH, BB), 128, FLASH_SMEM_BYTES>>>(qp, kp, vp, op);

    mma_gemm_nt<<<dim3(DD / 128, M / 128), 256, MMA_GEMM_SMEM>>>(op, wo, out, DD);
}